// round 5
// baseline (speedup 1.0000x reference)
#include <cuda_runtime.h>
#include <cuda_fp16.h>

#define BB 4
#define CC 64
#define FD 50000
#define KN 16
#define BN_EPS 1e-5f

// Scratch: transformed features g[b][f][o] in fp16 (face-major, 128B rows)
__device__ __half g_buf[BB * FD * CC];
__device__ float g_sum[CC];
__device__ float g_sq[CC];

// ---------------------------------------------------------------------------
// Packed f32x2 helpers (Blackwell FFMA2 path — ptxas won't auto-fuse this)
__device__ __forceinline__ unsigned long long pk2(float x, float y) {
    unsigned long long r;
    asm("mov.b64 %0, {%1, %2};" : "=l"(r) : "f"(x), "f"(y));
    return r;
}
__device__ __forceinline__ void upk2(unsigned long long v, float& x, float& y) {
    asm("mov.b64 {%0, %1}, %2;" : "=f"(x), "=f"(y) : "l"(v));
}
__device__ __forceinline__ void fma2(unsigned long long& d,
                                     unsigned long long a,
                                     unsigned long long b) {
    asm("fma.rn.f32x2 %0, %1, %2, %0;" : "+l"(d) : "l"(a), "l"(b));
}

// ---------------------------------------------------------------------------
// GEMM: g[b][f][o] = sum_c W[o][c] * fea[b][c][f], fp16 output.
// Direct-LDG mainloop (fea is consumed by exactly one thread -> no staging),
// only W lives in shared (16 KB). No barriers in the hot loop.
// Block: 256 threads, tile 128 faces x 64 outputs; thread: 4 faces x 8 outputs.
__global__ __launch_bounds__(256) void gemm_kernel(const float* __restrict__ fea,
                                                   const float* __restrict__ W) {
    __shared__ float2 sW2[64][32];    // [c][o/2]  16 KB, pair loads as LDS.64
    const int b = blockIdx.y;
    const int f0 = blockIdx.x * 128;
    const int t = threadIdx.x;

    // fold stats zeroing into this kernel (runs before gather)
    if (f0 == 0 && b == 0 && t < CC) { g_sum[t] = 0.f; g_sq[t] = 0.f; }

    // sW2[c][jj] = (W[2jj][c], W[2jj+1][c])
    for (int i = t; i < 64 * 32; i += 256) {
        int c = i >> 5, jj = i & 31;
        sW2[c][jj] = make_float2(W[(2 * jj) * CC + c], W[(2 * jj + 1) * CC + c]);
    }
    __syncthreads();

    const int tx = t & 31;   // face lane
    const int ty = t >> 5;   // output group 0..7 (outputs ty*8 .. ty*8+7)

    // c-invariant validity predicates (only the last f-tile is partial)
    const bool p0 = (f0 + tx)      < FD;
    const bool p1 = (f0 + tx + 32) < FD;
    const bool p2 = (f0 + tx + 64) < FD;
    const bool p3 = (f0 + tx + 96) < FD;

    const float* feap = fea + (size_t)b * (CC * FD) + f0 + tx;

    unsigned long long acc2[4][4];
#pragma unroll
    for (int i = 0; i < 4; i++)
#pragma unroll
        for (int j = 0; j < 4; j++) acc2[i][j] = 0ull;

#pragma unroll 4
    for (int c = 0; c < 64; c++) {
        const float* fc = feap + c * FD;
        float a0 = p0 ? fc[0]  : 0.f;    // coalesced 128B/warp segments
        float a1 = p1 ? fc[32] : 0.f;
        float a2 = p2 ? fc[64] : 0.f;
        float a3 = p3 ? fc[96] : 0.f;
        unsigned long long pa0 = pk2(a0, a0);
        unsigned long long pa1 = pk2(a1, a1);
        unsigned long long pa2 = pk2(a2, a2);
        unsigned long long pa3 = pk2(a3, a3);
#pragma unroll
        for (int jj = 0; jj < 4; jj++) {
            unsigned long long w2 =
                *(const unsigned long long*)&sW2[c][ty * 4 + jj];  // broadcast LDS.64
            fma2(acc2[0][jj], pa0, w2);
            fma2(acc2[1][jj], pa1, w2);
            fma2(acc2[2][jj], pa2, w2);
            fma2(acc2[3][jj], pa3, w2);
        }
    }

    __half* gb = g_buf + (size_t)b * (FD * CC);
#pragma unroll
    for (int i = 0; i < 4; i++) {
        int fg = f0 + tx + 32 * i;
        if (fg < FD) {
            union { __half2 h[4]; uint4 u; } pk;
#pragma unroll
            for (int jj = 0; jj < 4; jj++) {
                float lo, hi;
                upk2(acc2[i][jj], lo, hi);
                pk.h[jj] = __floats2half2_rn(lo, hi);
            }
            *(uint4*)(gb + (size_t)fg * CC + ty * 8) = pk.u;  // 16B store
        }
    }
}

// ---------------------------------------------------------------------------
// Gather + bias + stats, writes y into d_out in [B, C, F] layout.
// Warp per 4 faces; lane owns channels (2*lane, 2*lane+1) -> one half2 LDG.32
// per neighbor row (warp covers the full 128B row). fp32 accumulation.
__global__ __launch_bounds__(256) void gather_kernel(const int* __restrict__ ring,
                                                     const float* __restrict__ bias,
                                                     float* __restrict__ out) {
    __shared__ float tile[32][65];      // [f_local][c], padded
    __shared__ float s_sum[CC];
    __shared__ float s_sq[CC];

    const int t = threadIdx.x;
    if (t < CC) { s_sum[t] = 0.f; s_sq[t] = 0.f; }
    __syncthreads();

    const int b = blockIdx.y;
    const int f0 = blockIdx.x * 32;
    const int warp = t >> 5, lane = t & 31;
    const __half2* gb = (const __half2*)(g_buf + (size_t)b * (FD * CC));
    const float bias0 = bias[2 * lane];
    const float bias1 = bias[2 * lane + 1];

    float s0 = 0.f, s1 = 0.f, q0 = 0.f, q1 = 0.f;

#pragma unroll
    for (int i = 0; i < 4; i++) {
        int f = f0 + warp * 4 + i;              // warp-uniform
        if (f >= FD) continue;
        const int* rp = ring + ((long long)(b * FD + f)) * KN;
        int myidx = (lane < KN) ? rp[lane] : 0;
        if ((unsigned)myidx >= (unsigned)FD) myidx = 0;   // defensive
        float accx = 0.f, accy = 0.f;
#pragma unroll
        for (int k = 0; k < KN; k++) {
            int idx = __shfl_sync(0xffffffffu, myidx, k);
            float2 v = __half22float2(gb[(size_t)idx * 32 + lane]);
            accx += v.x;
            accy += v.y;
        }
        float y0 = accx + bias0;
        float y1 = accy + bias1;
        tile[warp * 4 + i][2 * lane]     = y0;
        tile[warp * 4 + i][2 * lane + 1] = y1;
        s0 += y0; q0 += y0 * y0;
        s1 += y1; q1 += y1 * y1;
    }

    atomicAdd(&s_sum[2 * lane],     s0);
    atomicAdd(&s_sum[2 * lane + 1], s1);
    atomicAdd(&s_sq[2 * lane],      q0);
    atomicAdd(&s_sq[2 * lane + 1],  q1);
    __syncthreads();

    // Transposed, coalesced write: out[b][c][f0+lane]
    const int nf = min(32, FD - f0);
    for (int c = warp; c < CC; c += 8) {
        if (lane < nf)
            out[((size_t)b * CC + c) * FD + f0 + lane] = tile[lane][c];
    }

    if (t < CC) {
        atomicAdd(&g_sum[t], s_sum[t]);
        atomicAdd(&g_sq[t],  s_sq[t]);
    }
}

// ---------------------------------------------------------------------------
// In-place normalize + ReLU over d_out, float4 vectorized, BN finalize inline.
// 3,200,000 float4 = 12500 blocks x 256 threads exactly.
__global__ __launch_bounds__(256) void norm_kernel(const float* __restrict__ gamma,
                                                   const float* __restrict__ beta,
                                                   float* __restrict__ out) {
    int i = blockIdx.x * 256 + threadIdx.x;       // float4 index
    int c = (i / (FD / 4)) & 63;                  // channel
    const float inv_n = 1.0f / (float)(BB * FD);
    float mean = g_sum[c] * inv_n;
    float var  = g_sq[c] * inv_n - mean * mean;
    float sc = gamma[c] * rsqrtf(var + BN_EPS);
    float sh = beta[c] - mean * sc;
    float4 v = ((float4*)out)[i];
    v.x = fmaxf(fmaf(v.x, sc, sh), 0.f);
    v.y = fmaxf(fmaf(v.y, sc, sh), 0.f);
    v.z = fmaxf(fmaf(v.z, sc, sh), 0.f);
    v.w = fmaxf(fmaf(v.w, sc, sh), 0.f);
    ((float4*)out)[i] = v;
}

// ---------------------------------------------------------------------------
extern "C" void kernel_launch(void* const* d_in, const int* in_sizes, int n_in,
                              void* d_out, int out_size) {
    const float* fea   = (const float*)d_in[0];      // [B, C_in, F]
    const int*   ring  = (const int*)d_in[1];        // [B, F, K] int32
    const float* W     = (const float*)d_in[2];      // [C_out, C_in]
    const float* bias  = (const float*)d_in[3];      // [C_out]
    const float* gamma = (const float*)d_in[4];      // [C_out]
    const float* beta  = (const float*)d_in[5];      // [C_out]
    float*       out   = (float*)d_out;              // [B, C_out, F]

    dim3 gg((FD + 127) / 128, BB);
    gemm_kernel<<<gg, 256>>>(fea, W);

    dim3 gt((FD + 31) / 32, BB);
    gather_kernel<<<gt, 256>>>(ring, bias, out);

    norm_kernel<<<(BB * CC * FD / 4) / 256, 256>>>(gamma, beta, out);
}

// round 6
// speedup vs baseline: 1.6578x; 1.6578x over previous
#include <cuda_runtime.h>
#include <cuda_fp16.h>

#define BB 4
#define CC 64
#define FD 50000
#define KN 16
#define BN_EPS 1e-5f

// Scratch: transformed features g[b][f][o] in fp16 (face-major, 128B rows)
__device__ __half g_buf[BB * FD * CC];
__device__ float g_sum[CC];
__device__ float g_sq[CC];

// ---------------------------------------------------------------------------
// Packed f32x2 helpers (Blackwell FFMA2 path — ptxas won't auto-fuse this)
__device__ __forceinline__ unsigned long long pk2(float x, float y) {
    unsigned long long r;
    asm("mov.b64 %0, {%1, %2};" : "=l"(r) : "f"(x), "f"(y));
    return r;
}
__device__ __forceinline__ void upk2(unsigned long long v, float& x, float& y) {
    asm("mov.b64 {%0, %1}, %2;" : "=f"(x), "=f"(y) : "l"(v));
}
__device__ __forceinline__ void fma2(unsigned long long& d,
                                     unsigned long long a,
                                     unsigned long long b) {
    asm("fma.rn.f32x2 %0, %1, %2, %0;" : "+l"(d) : "l"(a), "l"(b));
}

// ---------------------------------------------------------------------------
// GEMM: g[b][f][o] = sum_c W[o][c] * fea[b][c][f], fp16 output.
// Staged-smem (batched MLP on the gmem loads), consecutive-face float4
// microtile, float4 W broadcasts (f32x2 pairs fall out of the 16B words free).
// Block: 256 threads, tile 128 faces x 64 outputs; thread: 4 faces x 8 outputs.
__global__ __launch_bounds__(256) void gemm_kernel(const float* __restrict__ fea,
                                                   const float* __restrict__ W) {
    __shared__ float  sF[64][128];    // [c][f]          32 KB
    __shared__ float4 sW4[64][16];    // [c][o/4] quads  16 KB
    const int b = blockIdx.y;
    const int f0 = blockIdx.x * 128;
    const int t = threadIdx.x;
    const int warp = t >> 5, lane = t & 31;

    // fold stats zeroing into this kernel (runs before gather)
    if (f0 == 0 && b == 0 && t < CC) { g_sum[t] = 0.f; g_sq[t] = 0.f; }

    // Stage fea tile: warp per c-row, float4 lanes. nv is a multiple of 4.
    const float* feab = fea + (size_t)b * (CC * FD);
    const int nv = min(128, FD - f0);
    for (int c = warp; c < 64; c += 8) {
        const float* src = feab + c * FD + f0;
        float4 v = make_float4(0.f, 0.f, 0.f, 0.f);
        if (4 * lane + 3 < nv) v = *(const float4*)(src + 4 * lane);
        ((float4*)&sF[c][0])[lane] = v;
    }
    // sW4[c][j] = (W[4j][c], W[4j+1][c], W[4j+2][c], W[4j+3][c])
    for (int i = t; i < 64 * 16; i += 256) {
        int c = i >> 4, j = i & 15;
        sW4[c][j] = make_float4(W[(4 * j) * CC + c], W[(4 * j + 1) * CC + c],
                                W[(4 * j + 2) * CC + c], W[(4 * j + 3) * CC + c]);
    }
    __syncthreads();

    const int tx = t & 31;   // face quad: faces 4tx .. 4tx+3
    const int ty = t >> 5;   // output group: outputs ty*8 .. ty*8+7

    unsigned long long acc2[4][4];   // [face][output pair]
#pragma unroll
    for (int i = 0; i < 4; i++)
#pragma unroll
        for (int j = 0; j < 4; j++) acc2[i][j] = 0ull;

#pragma unroll 4
    for (int c = 0; c < 64; c++) {
        float4 a = ((const float4*)&sF[c][0])[tx];                 // LDS.128
        ulonglong2 wA = ((const ulonglong2*)&sW4[c][0])[2 * ty];   // bcast LDS.128
        ulonglong2 wB = ((const ulonglong2*)&sW4[c][0])[2 * ty + 1];
        unsigned long long pa0 = pk2(a.x, a.x);
        unsigned long long pa1 = pk2(a.y, a.y);
        unsigned long long pa2 = pk2(a.z, a.z);
        unsigned long long pa3 = pk2(a.w, a.w);
        // wA.x = outputs (8ty,8ty+1), wA.y = (+2,+3), wB.x = (+4,+5), wB.y = (+6,+7)
        fma2(acc2[0][0], pa0, wA.x); fma2(acc2[0][1], pa0, wA.y);
        fma2(acc2[0][2], pa0, wB.x); fma2(acc2[0][3], pa0, wB.y);
        fma2(acc2[1][0], pa1, wA.x); fma2(acc2[1][1], pa1, wA.y);
        fma2(acc2[1][2], pa1, wB.x); fma2(acc2[1][3], pa1, wB.y);
        fma2(acc2[2][0], pa2, wA.x); fma2(acc2[2][1], pa2, wA.y);
        fma2(acc2[2][2], pa2, wB.x); fma2(acc2[2][3], pa2, wB.y);
        fma2(acc2[3][0], pa3, wA.x); fma2(acc2[3][1], pa3, wA.y);
        fma2(acc2[3][2], pa3, wB.x); fma2(acc2[3][3], pa3, wB.y);
    }

    __half* gb = g_buf + (size_t)b * (FD * CC);
#pragma unroll
    for (int i = 0; i < 4; i++) {
        int fg = f0 + 4 * tx + i;
        if (fg < FD) {
            union { __half2 h[4]; uint4 u; } pk;
#pragma unroll
            for (int jj = 0; jj < 4; jj++) {
                float lo, hi;
                upk2(acc2[i][jj], lo, hi);
                pk.h[jj] = __floats2half2_rn(lo, hi);
            }
            *(uint4*)(gb + (size_t)fg * CC + ty * 8) = pk.u;  // 16B store
        }
    }
}

// ---------------------------------------------------------------------------
// Gather + bias + stats, writes y into d_out in [B, C, F] layout.
// Warp per 4 faces; lane owns channels (2*lane, 2*lane+1) -> one half2 LDG.32
// per neighbor row (warp covers the full 128B row). fp32 accumulation.
__global__ __launch_bounds__(256) void gather_kernel(const int* __restrict__ ring,
                                                     const float* __restrict__ bias,
                                                     float* __restrict__ out) {
    __shared__ float tile[32][65];      // [f_local][c], padded
    __shared__ float s_sum[CC];
    __shared__ float s_sq[CC];

    const int t = threadIdx.x;
    if (t < CC) { s_sum[t] = 0.f; s_sq[t] = 0.f; }
    __syncthreads();

    const int b = blockIdx.y;
    const int f0 = blockIdx.x * 32;
    const int warp = t >> 5, lane = t & 31;
    const __half2* gb = (const __half2*)(g_buf + (size_t)b * (FD * CC));
    const float bias0 = bias[2 * lane];
    const float bias1 = bias[2 * lane + 1];

    float s0 = 0.f, s1 = 0.f, q0 = 0.f, q1 = 0.f;

#pragma unroll
    for (int i = 0; i < 4; i++) {
        int f = f0 + warp * 4 + i;              // warp-uniform
        if (f >= FD) continue;
        const int* rp = ring + ((long long)(b * FD + f)) * KN;
        int myidx = (lane < KN) ? rp[lane] : 0;
        if ((unsigned)myidx >= (unsigned)FD) myidx = 0;   // defensive
        float accx = 0.f, accy = 0.f;
#pragma unroll
        for (int k = 0; k < KN; k++) {
            int idx = __shfl_sync(0xffffffffu, myidx, k);
            float2 v = __half22float2(gb[(size_t)idx * 32 + lane]);
            accx += v.x;
            accy += v.y;
        }
        float y0 = accx + bias0;
        float y1 = accy + bias1;
        tile[warp * 4 + i][2 * lane]     = y0;
        tile[warp * 4 + i][2 * lane + 1] = y1;
        s0 += y0; q0 += y0 * y0;
        s1 += y1; q1 += y1 * y1;
    }

    atomicAdd(&s_sum[2 * lane],     s0);
    atomicAdd(&s_sum[2 * lane + 1], s1);
    atomicAdd(&s_sq[2 * lane],      q0);
    atomicAdd(&s_sq[2 * lane + 1],  q1);
    __syncthreads();

    // Transposed, coalesced write: out[b][c][f0+lane]
    const int nf = min(32, FD - f0);
    for (int c = warp; c < CC; c += 8) {
        if (lane < nf)
            out[((size_t)b * CC + c) * FD + f0 + lane] = tile[lane][c];
    }

    if (t < CC) {
        atomicAdd(&g_sum[t], s_sum[t]);
        atomicAdd(&g_sq[t],  s_sq[t]);
    }
}

// ---------------------------------------------------------------------------
// In-place normalize + ReLU over d_out, float4 vectorized, BN finalize inline.
// 3,200,000 float4 = 12500 blocks x 256 threads exactly.
__global__ __launch_bounds__(256) void norm_kernel(const float* __restrict__ gamma,
                                                   const float* __restrict__ beta,
                                                   float* __restrict__ out) {
    int i = blockIdx.x * 256 + threadIdx.x;       // float4 index
    int c = (i / (FD / 4)) & 63;                  // channel
    const float inv_n = 1.0f / (float)(BB * FD);
    float mean = g_sum[c] * inv_n;
    float var  = g_sq[c] * inv_n - mean * mean;
    float sc = gamma[c] * rsqrtf(var + BN_EPS);
    float sh = beta[c] - mean * sc;
    float4 v = ((float4*)out)[i];
    v.x = fmaxf(fmaf(v.x, sc, sh), 0.f);
    v.y = fmaxf(fmaf(v.y, sc, sh), 0.f);
    v.z = fmaxf(fmaf(v.z, sc, sh), 0.f);
    v.w = fmaxf(fmaf(v.w, sc, sh), 0.f);
    ((float4*)out)[i] = v;
}

// ---------------------------------------------------------------------------
extern "C" void kernel_launch(void* const* d_in, const int* in_sizes, int n_in,
                              void* d_out, int out_size) {
    const float* fea   = (const float*)d_in[0];      // [B, C_in, F]
    const int*   ring  = (const int*)d_in[1];        // [B, F, K] int32
    const float* W     = (const float*)d_in[2];      // [C_out, C_in]
    const float* bias  = (const float*)d_in[3];      // [C_out]
    const float* gamma = (const float*)d_in[4];      // [C_out]
    const float* beta  = (const float*)d_in[5];      // [C_out]
    float*       out   = (float*)d_out;              // [B, C_out, F]

    dim3 gg((FD + 127) / 128, BB);
    gemm_kernel<<<gg, 256>>>(fea, W);

    dim3 gt((FD + 31) / 32, BB);
    gather_kernel<<<gt, 256>>>(ring, bias, out);

    norm_kernel<<<(BB * CC * FD / 4) / 256, 256>>>(gamma, beta, out);
}